// round 8
// baseline (speedup 1.0000x reference)
#include <cuda_runtime.h>

#define Bn 8
#define Sn 1024
#define INn 512
#define DMn 1024
#define Hn 16
#define DEPTHn 64
#define Mn (Bn * Sn)   // 8192

// ---------------- scratch (static device globals; no allocs) ----------------
__device__ float g_q[Bn * Hn * Sn * DEPTHn];
__device__ float g_k[Bn * Hn * Sn * DEPTHn];
__device__ float g_v[Bn * Hn * Sn * DEPTHn];
__device__ float g_res[Mn * DMn];
__device__ float g_o[Mn * DMn];
__device__ float g_y[Mn * DMn];

// ---------------- GEMM: C[M x 1024] = A[M x K] * W[K x 1024] (+bias)(+res) --
// 128x128 tile, BK=16, 256 threads, 8x8 per thread (4+4 split rows/cols).
template <bool HEAD>
__global__ __launch_bounds__(256, 2)
void gemm_kernel(const float* __restrict__ A, int lda, int K,
                 const float* __restrict__ W,
                 const float* __restrict__ bias,
                 const float* __restrict__ res,
                 float* __restrict__ out)
{
    __shared__ float As[16][128];
    __shared__ float Bs[16][128];

    const int t  = threadIdx.x;
    const int tx = t & 15, ty = t >> 4;
    const int mBase = blockIdx.y << 7;
    const int nBase = blockIdx.x << 7;

    const int arow = t >> 2, acol = (t & 3) << 2;   // A: 128 rows x 16 k
    const int brow = t >> 5, bcol = (t & 31) << 2;  // B: 16 k x 128 cols

    float c[8][8];
#pragma unroll
    for (int i = 0; i < 8; i++)
#pragma unroll
        for (int j = 0; j < 8; j++) c[i][j] = 0.f;

    const float* Ag  = A + (size_t)(mBase + arow) * lda + acol;
    const float* Ag2 = Ag + (size_t)64 * lda;
    const float* Bg  = W + (size_t)brow * 1024 + nBase + bcol;

    for (int kk = 0; kk < K; kk += 16) {
        float4 a0 = *(const float4*)(Ag + kk);
        float4 a1 = *(const float4*)(Ag2 + kk);
        float4 b0 = *(const float4*)(Bg + (size_t)kk * 1024);
        float4 b1 = *(const float4*)(Bg + (size_t)(kk + 8) * 1024);
        __syncthreads();
        As[acol + 0][arow] = a0.x; As[acol + 1][arow] = a0.y;
        As[acol + 2][arow] = a0.z; As[acol + 3][arow] = a0.w;
        As[acol + 0][arow + 64] = a1.x; As[acol + 1][arow + 64] = a1.y;
        As[acol + 2][arow + 64] = a1.z; As[acol + 3][arow + 64] = a1.w;
        *(float4*)&Bs[brow][bcol]     = b0;
        *(float4*)&Bs[brow + 8][bcol] = b1;
        __syncthreads();
#pragma unroll
        for (int k = 0; k < 16; k++) {
            float4 aa0 = *(const float4*)&As[k][ty * 4];
            float4 aa1 = *(const float4*)&As[k][ty * 4 + 64];
            float4 bb0 = *(const float4*)&Bs[k][tx * 4];
            float4 bb1 = *(const float4*)&Bs[k][tx * 4 + 64];
            float av[8] = {aa0.x, aa0.y, aa0.z, aa0.w, aa1.x, aa1.y, aa1.z, aa1.w};
            float bv[8] = {bb0.x, bb0.y, bb0.z, bb0.w, bb1.x, bb1.y, bb1.z, bb1.w};
#pragma unroll
            for (int i = 0; i < 8; i++)
#pragma unroll
                for (int j = 0; j < 8; j++)
                    c[i][j] = fmaf(av[i], bv[j], c[i][j]);
        }
    }

#pragma unroll
    for (int i = 0; i < 8; i++) {
        int m = mBase + ty * 4 + (i < 4 ? i : 60 + i);
#pragma unroll
        for (int jh = 0; jh < 2; jh++) {
            int n = nBase + tx * 4 + jh * 64;
            float4 v = make_float4(c[i][jh * 4 + 0], c[i][jh * 4 + 1],
                                   c[i][jh * 4 + 2], c[i][jh * 4 + 3]);
            if (bias) {
                float4 bb = *(const float4*)(bias + n);
                v.x += bb.x; v.y += bb.y; v.z += bb.z; v.w += bb.w;
            }
            if (res) {
                float4 rr = *(const float4*)(res + (size_t)m * 1024 + n);
                v.x += rr.x; v.y += rr.y; v.z += rr.z; v.w += rr.w;
            }
            if (HEAD) {
                int b_ = m >> 10, s_ = m & 1023;
                int h_ = n >> 6,  d_ = n & 63;
                *(float4*)(out + ((size_t)((b_ * Hn + h_) * Sn + s_) << 6) + d_) = v;
            } else {
                *(float4*)(out + (size_t)m * 1024 + n) = v;
            }
        }
    }
}

// ---------------- Flash attention, fp32, 64-query tiles ----------------
// grid (S/64, H, B), 128 threads. tx = key/d column group (8 wide),
// ty = query row group (4 wide). Online softmax; P staged via smem (transposed).
__global__ __launch_bounds__(128)
void attn_kernel(const int* __restrict__ mask)
{
    extern __shared__ float sm[];
    float (*Qs)[68] = (float(*)[68])(sm);                 // [d][m]
    float (*Ks)[68] = (float(*)[68])(sm + 64 * 68);       // [d][n]
    float (*Vs)[68] = (float(*)[68])(sm + 2 * 64 * 68);   // [n][d]
    float (*Ps)[68] = (float(*)[68])(sm + 3 * 64 * 68);   // [n][m]

    const int t  = threadIdx.x;
    const int tx = t & 7, ty = t >> 3;
    const int qb = blockIdx.x << 6;
    const int h  = blockIdx.y, b = blockIdx.z;

    const float* Qp    = g_q + ((size_t)((b * Hn + h) * Sn) + qb) * 64;
    const float* Kbase = g_k + (size_t)((b * Hn + h) * Sn) * 64;
    const float* Vbase = g_v + (size_t)((b * Hn + h) * Sn) * 64;
    const int*   mp    = mask + (size_t)h * Sn * Sn;

    {   // load Q tile transposed
        int r = t >> 1, d0 = (t & 1) << 5;
#pragma unroll
        for (int c = 0; c < 32; c += 4) {
            float4 v = *(const float4*)(Qp + r * 64 + d0 + c);
            Qs[d0 + c + 0][r] = v.x; Qs[d0 + c + 1][r] = v.y;
            Qs[d0 + c + 2][r] = v.z; Qs[d0 + c + 3][r] = v.w;
        }
    }

    float o[4][8];
    float mrun[4], lsum[4];
#pragma unroll
    for (int i = 0; i < 4; i++) {
        mrun[i] = -3.0e38f; lsum[i] = 0.f;
#pragma unroll
        for (int j = 0; j < 8; j++) o[i][j] = 0.f;
    }

    for (int kt = 0; kt < 16; kt++) {
        __syncthreads();
        {   // load K (transposed) and V tiles
            int r = t >> 1, d0 = (t & 1) << 5;
            const float* Kq = Kbase + (size_t)(kt * 64 + r) * 64 + d0;
            const float* Vq = Vbase + (size_t)(kt * 64 + r) * 64 + d0;
#pragma unroll
            for (int c = 0; c < 32; c += 4) {
                float4 v = *(const float4*)(Kq + c);
                Ks[d0 + c + 0][r] = v.x; Ks[d0 + c + 1][r] = v.y;
                Ks[d0 + c + 2][r] = v.z; Ks[d0 + c + 3][r] = v.w;
                float4 w = *(const float4*)(Vq + c);
                *(float4*)&Vs[r][d0 + c] = w;
            }
        }
        __syncthreads();

        float s[4][8];
#pragma unroll
        for (int i = 0; i < 4; i++)
#pragma unroll
            for (int j = 0; j < 8; j++) s[i][j] = 0.f;

#pragma unroll 8
        for (int d = 0; d < 64; d++) {
            float4 a  = *(const float4*)&Qs[d][ty * 4];
            float4 k0 = *(const float4*)&Ks[d][tx * 8];
            float4 k1 = *(const float4*)&Ks[d][tx * 8 + 4];
            float av[4] = {a.x, a.y, a.z, a.w};
            float kv[8] = {k0.x, k0.y, k0.z, k0.w, k1.x, k1.y, k1.z, k1.w};
#pragma unroll
            for (int i = 0; i < 4; i++)
#pragma unroll
                for (int j = 0; j < 8; j++)
                    s[i][j] = fmaf(av[i], kv[j], s[i][j]);
        }

        // scale + mask (matches reference: scores*scale, then mask==0 -> -1e9)
#pragma unroll
        for (int i = 0; i < 4; i++) {
            const int* mr = mp + (size_t)(qb + ty * 4 + i) * Sn + (kt << 6) + tx * 8;
            int4 m0 = *(const int4*)mr;
            int4 m1 = *(const int4*)(mr + 4);
            int mv[8] = {m0.x, m0.y, m0.z, m0.w, m1.x, m1.y, m1.z, m1.w};
#pragma unroll
            for (int j = 0; j < 8; j++)
                s[i][j] = mv[j] ? s[i][j] * 0.125f : -1e9f;
        }

        // online softmax (row groups of 8 lanes share the same ty -> shfl over 8)
#pragma unroll
        for (int i = 0; i < 4; i++) {
            float tm = s[i][0];
#pragma unroll
            for (int j = 1; j < 8; j++) tm = fmaxf(tm, s[i][j]);
            tm = fmaxf(tm, __shfl_xor_sync(0xffffffffu, tm, 1));
            tm = fmaxf(tm, __shfl_xor_sync(0xffffffffu, tm, 2));
            tm = fmaxf(tm, __shfl_xor_sync(0xffffffffu, tm, 4));
            float mn   = fmaxf(mrun[i], tm);
            float corr = __expf(mrun[i] - mn);
            mrun[i] = mn;
            float rs = 0.f;
#pragma unroll
            for (int j = 0; j < 8; j++) {
                float p = __expf(s[i][j] - mn);
                s[i][j] = p; rs += p;
            }
            rs += __shfl_xor_sync(0xffffffffu, rs, 1);
            rs += __shfl_xor_sync(0xffffffffu, rs, 2);
            rs += __shfl_xor_sync(0xffffffffu, rs, 4);
            lsum[i] = lsum[i] * corr + rs;
#pragma unroll
            for (int j = 0; j < 8; j++) o[i][j] *= corr;
        }

        // stage P transposed: Ps[n][m]
#pragma unroll
        for (int j = 0; j < 8; j++)
#pragma unroll
            for (int i = 0; i < 4; i++)
                Ps[tx * 8 + j][ty * 4 + i] = s[i][j];
        __syncthreads();

        // O += P * V
#pragma unroll 8
        for (int n = 0; n < 64; n++) {
            float4 a  = *(const float4*)&Ps[n][ty * 4];
            float4 v0 = *(const float4*)&Vs[n][tx * 8];
            float4 v1 = *(const float4*)&Vs[n][tx * 8 + 4];
            float av[4] = {a.x, a.y, a.z, a.w};
            float vv[8] = {v0.x, v0.y, v0.z, v0.w, v1.x, v1.y, v1.z, v1.w};
#pragma unroll
            for (int i = 0; i < 4; i++)
#pragma unroll
                for (int j = 0; j < 8; j++)
                    o[i][j] = fmaf(av[i], vv[j], o[i][j]);
        }
    }

#pragma unroll
    for (int i = 0; i < 4; i++) {
        float inv = 1.0f / lsum[i];
        float* op = g_o + (size_t)(b * Sn + qb + ty * 4 + i) * 1024 + h * 64 + tx * 8;
        float4 v0 = make_float4(o[i][0] * inv, o[i][1] * inv, o[i][2] * inv, o[i][3] * inv);
        float4 v1 = make_float4(o[i][4] * inv, o[i][5] * inv, o[i][6] * inv, o[i][7] * inv);
        *(float4*)op       = v0;
        *(float4*)(op + 4) = v1;
    }
}

// ---------------- LayerNorm over last dim (1024), one row per block ----------
__global__ __launch_bounds__(256)
void ln_kernel(const float* __restrict__ gamma, const float* __restrict__ beta,
               float* __restrict__ out)
{
    __shared__ float red[8];
    const int row = blockIdx.x, t = threadIdx.x;
    const int lane = t & 31, w = t >> 5;

    float4 v = *(const float4*)(g_y + (size_t)row * 1024 + t * 4);

    float su = v.x + v.y + v.z + v.w;
#pragma unroll
    for (int off = 16; off; off >>= 1) su += __shfl_xor_sync(0xffffffffu, su, off);
    if (lane == 0) red[w] = su;
    __syncthreads();
    if (w == 0) {
        float r = (lane < 8) ? red[lane] : 0.f;
#pragma unroll
        for (int off = 4; off; off >>= 1) r += __shfl_xor_sync(0xffffffffu, r, off);
        if (lane == 0) red[0] = r;
    }
    __syncthreads();
    float mu = red[0] * (1.0f / 1024.0f);
    __syncthreads();

    float dx = v.x - mu, dy = v.y - mu, dz = v.z - mu, dw = v.w - mu;
    float sq = dx * dx + dy * dy + dz * dz + dw * dw;
#pragma unroll
    for (int off = 16; off; off >>= 1) sq += __shfl_xor_sync(0xffffffffu, sq, off);
    if (lane == 0) red[w] = sq;
    __syncthreads();
    if (w == 0) {
        float r = (lane < 8) ? red[lane] : 0.f;
#pragma unroll
        for (int off = 4; off; off >>= 1) r += __shfl_xor_sync(0xffffffffu, r, off);
        if (lane == 0) red[0] = r;
    }
    __syncthreads();
    float var  = red[0] * (1.0f / 1024.0f);
    float rstd = rsqrtf(var + 1e-5f);

    float4 gg = *(const float4*)(gamma + t * 4);
    float4 bb = *(const float4*)(beta + t * 4);
    float4 ov = make_float4(dx * rstd * gg.x + bb.x, dy * rstd * gg.y + bb.y,
                            dz * rstd * gg.z + bb.z, dw * rstd * gg.w + bb.w);
    *(float4*)(out + (size_t)row * 1024 + t * 4) = ov;
}

// ---------------- launch ----------------
extern "C" void kernel_launch(void* const* d_in, const int* in_sizes, int n_in,
                              void* d_out, int out_size)
{
    const float* x    = (const float*)d_in[0];
    const int*   mask = (const int*)  d_in[1];
    const float* wq   = (const float*)d_in[2];
    const float* bq   = (const float*)d_in[3];
    const float* wk   = (const float*)d_in[4];
    const float* bk   = (const float*)d_in[5];
    const float* wv   = (const float*)d_in[6];
    const float* bv   = (const float*)d_in[7];
    const float* dw   = (const float*)d_in[8];
    const float* db   = (const float*)d_in[9];
    const float* rw   = (const float*)d_in[10];
    const float* lg   = (const float*)d_in[11];
    const float* lb   = (const float*)d_in[12];
    float* out = (float*)d_out;

    float *gq, *gk, *gv, *gres, *go, *gy;
    cudaGetSymbolAddress((void**)&gq,   g_q);
    cudaGetSymbolAddress((void**)&gk,   g_k);
    cudaGetSymbolAddress((void**)&gv,   g_v);
    cudaGetSymbolAddress((void**)&gres, g_res);
    cudaGetSymbolAddress((void**)&go,   g_o);
    cudaGetSymbolAddress((void**)&gy,   g_y);

    const int attn_smem = 4 * 64 * 68 * 4;  // 69632 B > 48K -> opt in
    cudaFuncSetAttribute(attn_kernel, cudaFuncAttributeMaxDynamicSharedMemorySize,
                         attn_smem);

    dim3 ggrid(8, 64), gthr(256);
    gemm_kernel<true ><<<ggrid, gthr>>>(x, 512, 512, wq, bq, nullptr, gq);
    gemm_kernel<true ><<<ggrid, gthr>>>(x, 512, 512, wk, bk, nullptr, gk);
    gemm_kernel<true ><<<ggrid, gthr>>>(x, 512, 512, wv, bv, nullptr, gv);
    gemm_kernel<false><<<ggrid, gthr>>>(x, 512, 512, rw, nullptr, nullptr, gres);

    attn_kernel<<<dim3(Sn / 64, Hn, Bn), 128, attn_smem>>>(mask);

    gemm_kernel<false><<<ggrid, gthr>>>(go, 1024, 1024, dw, db, gres, gy);

    ln_kernel<<<Mn, 256>>>(lg, lb, out);
}